// round 1
// baseline (speedup 1.0000x reference)
#include <cuda_runtime.h>
#include <cstdint>

// Problem constants
#define T_PADDED 65656          // T_SIM + T_KERNEL - 1
#define T_OUT    65536
#define NROWS    768            // SIZE * C
#define CCH      384
#define NB       168            // number of OA blocks
#define HOP      392            // block hop = block content length
#define BSZ      512            // FFT block size
#define OVL      120            // BSZ - HOP
#define KC       392            // GEMM1 K dim
#define NCOLS    (NROWS * NB)   // 129024 conv-GEMM columns

// Scratch (device globals: allocation-free rule)
__device__ float g_h[512];
__device__ float g_C[(size_t)NCOLS * 512];     // [col][j]  col = r*NB + b
__device__ float g_y[(size_t)NROWS * T_OUT];   // [r][t]

// ---------------------------------------------------------------------------
// Kernel 1: h = irfft(kernel_fft, n=512)  (standard norm)
// h[j] = (H[0] + (-1)^j H[256] + 2*sum_{m=1..255} H[m] cos(2*pi*m*j/512)) / 512
// ---------------------------------------------------------------------------
__global__ void k_irfft(const float* __restrict__ H) {
    int j = threadIdx.x;
    float acc = H[0] + ((j & 1) ? -H[256] : H[256]);
    const float w = 6.283185307179586476f / 512.0f;
    for (int m = 1; m < 256; m++) {
        int ph = (m * j) & 511;           // exploit periodicity for accurate reduction
        acc += 2.0f * H[m] * cosf(w * (float)ph);
    }
    g_h[j] = acc * (1.0f / 512.0f);
}

// ---------------------------------------------------------------------------
// Kernel 2: conv GEMM  C[col][j] = sum_k h[(j-k)&511] * noise[r, 392*b + k]
// M=512 (j), N=129024 (col=r*NB+b), K=392.
// CTA tile 128x128, k-tile 8, 256 threads, 8x8 register tile.
// ---------------------------------------------------------------------------
__global__ __launch_bounds__(256, 2) void k_conv_gemm(const float* __restrict__ noise) {
    __shared__ float sh[512];
    __shared__ float As[8][128];
    __shared__ float Bs[8][128];

    const int tid = threadIdx.x;
    const int m0 = blockIdx.y * 128;      // j base
    const int n0 = blockIdx.x * 128;      // col base

    // stage h into smem
    sh[tid] = g_h[tid];
    sh[tid + 256] = g_h[tid + 256];

    // B-load mapping: thread -> (col_in_tile, k quad)
    const int bcol = tid & 127;
    const int bkq  = (tid >> 7) * 4;      // 0 or 4
    const int col  = n0 + bcol;
    const int r    = col / NB;
    const int b    = col - r * NB;
    const float* __restrict__ xrow = noise + (size_t)r * T_PADDED;
    const int tbase = b * HOP;

    // A-build mapping: thread -> (k row, 4 consecutive m)
    const int a_k = tid >> 5;             // 0..7
    const int a_m = (tid & 31) * 4;       // 0..124

    // fragment bases
    const int fx = (tid & 15) * 4;        // n frag
    const int fy = (tid >> 4) * 4;        // m frag

    float acc[8][8];
#pragma unroll
    for (int i = 0; i < 8; i++)
#pragma unroll
        for (int j = 0; j < 8; j++) acc[i][j] = 0.0f;

    __syncthreads();                      // sh ready

    for (int k0 = 0; k0 < KC; k0 += 8) {
        // build A fragment values from circular h
        int base = (m0 + a_m - k0 - a_k) & 511;
        float4 av;
        av.x = sh[base];
        av.y = sh[(base + 1) & 511];
        av.z = sh[(base + 2) & 511];
        av.w = sh[(base + 3) & 511];

        // load B (zero-guarded tail; 4-aligned so float4 is all-in or all-out)
        int gk = tbase + k0 + bkq;
        float4 bv = make_float4(0.f, 0.f, 0.f, 0.f);
        if (gk < T_PADDED) bv = *reinterpret_cast<const float4*>(xrow + gk);

        __syncthreads();                  // previous inner loop done
        *reinterpret_cast<float4*>(&As[a_k][a_m]) = av;
        Bs[bkq + 0][bcol] = bv.x;
        Bs[bkq + 1][bcol] = bv.y;
        Bs[bkq + 2][bcol] = bv.z;
        Bs[bkq + 3][bcol] = bv.w;
        __syncthreads();

#pragma unroll
        for (int kk = 0; kk < 8; kk++) {
            float a[8], bb[8];
            *reinterpret_cast<float4*>(a)      = *reinterpret_cast<float4*>(&As[kk][fy]);
            *reinterpret_cast<float4*>(a + 4)  = *reinterpret_cast<float4*>(&As[kk][fy + 64]);
            *reinterpret_cast<float4*>(bb)     = *reinterpret_cast<float4*>(&Bs[kk][fx]);
            *reinterpret_cast<float4*>(bb + 4) = *reinterpret_cast<float4*>(&Bs[kk][fx + 64]);
#pragma unroll
            for (int i = 0; i < 8; i++)
#pragma unroll
                for (int j = 0; j < 8; j++) acc[i][j] += a[i] * bb[j];
        }
    }

    // epilogue: C[col][j], j contiguous -> gather across acc's m index
#pragma unroll
    for (int jn = 0; jn < 8; jn++) {
        int c = n0 + fx + (jn < 4 ? jn : jn + 60);
        float* base = g_C + (size_t)c * 512 + m0 + fy;
        *reinterpret_cast<float4*>(base)      = make_float4(acc[0][jn], acc[1][jn], acc[2][jn], acc[3][jn]);
        *reinterpret_cast<float4*>(base + 64) = make_float4(acc[4][jn], acc[5][jn], acc[6][jn], acc[7][jn]);
    }
}

// ---------------------------------------------------------------------------
// Kernel 3: overlap-add combine + slice
// y[r][t] = C[r*NB+b2][j2] + (j2 < 120 ? C[r*NB+b2-1][j2+392] : 0),
//   with p = t + 120, b2 = p/392, j2 = p%392
// ---------------------------------------------------------------------------
__global__ void k_combine() {
    int r = blockIdx.y;
    int t = blockIdx.x * 256 + threadIdx.x;
    int p = t + OVL;                      // s2 - 1 = 120
    int b2 = p / HOP;
    int j2 = p - b2 * HOP;
    size_t col = (size_t)r * NB + b2;
    float v = g_C[col * 512 + j2];
    if (j2 < OVL) v += g_C[(col - 1) * 512 + j2 + HOP];
    g_y[(size_t)r * T_OUT + t] = v;
}

// ---------------------------------------------------------------------------
// Kernel 4: out[n][t][d] = sum_c y[n*384+c][t] * (std[c]*vt[c][d])
// per n: (65536 x 384) @ (384 x 384). CTA tile 128(t) x 128(d), k-tile 8.
// ---------------------------------------------------------------------------
__global__ __launch_bounds__(256, 2) void k_out_gemm(const float* __restrict__ vt,
                                                     const float* __restrict__ sstd,
                                                     float* __restrict__ out) {
    __shared__ float As[8][128];          // [c][t]
    __shared__ float Bs[8][128];          // [c][d]

    const int tid = threadIdx.x;
    const int nz = blockIdx.z;
    const int t0 = blockIdx.y * 128;
    const int d0 = blockIdx.x * 128;

    const int c_l = tid >> 5;             // 0..7
    const int q4  = (tid & 31) * 4;       // 0..124

    const int fx = (tid & 15) * 4;        // d frag
    const int fy = (tid >> 4) * 4;        // t frag

    const float* __restrict__ ybase = g_y + (size_t)nz * CCH * T_OUT;

    float acc[8][8];
#pragma unroll
    for (int i = 0; i < 8; i++)
#pragma unroll
        for (int j = 0; j < 8; j++) acc[i][j] = 0.0f;

    for (int c0 = 0; c0 < CCH; c0 += 8) {
        float4 av = *reinterpret_cast<const float4*>(ybase + (size_t)(c0 + c_l) * T_OUT + t0 + q4);
        float sd = __ldg(sstd + c0 + c_l);
        float4 bv = *reinterpret_cast<const float4*>(vt + (size_t)(c0 + c_l) * CCH + d0 + q4);
        bv.x *= sd; bv.y *= sd; bv.z *= sd; bv.w *= sd;

        __syncthreads();
        *reinterpret_cast<float4*>(&As[c_l][q4]) = av;
        *reinterpret_cast<float4*>(&Bs[c_l][q4]) = bv;
        __syncthreads();

#pragma unroll
        for (int kk = 0; kk < 8; kk++) {
            float a[8], bb[8];
            *reinterpret_cast<float4*>(a)      = *reinterpret_cast<float4*>(&As[kk][fy]);
            *reinterpret_cast<float4*>(a + 4)  = *reinterpret_cast<float4*>(&As[kk][fy + 64]);
            *reinterpret_cast<float4*>(bb)     = *reinterpret_cast<float4*>(&Bs[kk][fx]);
            *reinterpret_cast<float4*>(bb + 4) = *reinterpret_cast<float4*>(&Bs[kk][fx + 64]);
#pragma unroll
            for (int i = 0; i < 8; i++)
#pragma unroll
                for (int j = 0; j < 8; j++) acc[i][j] += a[i] * bb[j];
        }
    }

    // epilogue: out[(nz*T_OUT + t)*384 + d], d contiguous
#pragma unroll
    for (int i = 0; i < 8; i++) {
        int t = t0 + fy + (i < 4 ? i : i + 60);
        float* base = out + ((size_t)(nz * T_OUT + t)) * CCH + d0 + fx;
        *reinterpret_cast<float4*>(base)      = make_float4(acc[i][0], acc[i][1], acc[i][2], acc[i][3]);
        *reinterpret_cast<float4*>(base + 64) = make_float4(acc[i][4], acc[i][5], acc[i][6], acc[i][7]);
    }
}

// ---------------------------------------------------------------------------
extern "C" void kernel_launch(void* const* d_in, const int* in_sizes, int n_in,
                              void* d_out, int out_size) {
    const float* noise = (const float*)d_in[0];   // [768, 65656]
    const float* sstd  = (const float*)d_in[1];   // [384]
    const float* vt    = (const float*)d_in[2];   // [384, 384]
    const float* H     = (const float*)d_in[3];   // [257]
    float* out = (float*)d_out;                   // [2, 65536, 384]

    k_irfft<<<1, 512>>>(H);

    dim3 g1(NCOLS / 128, 512 / 128);              // (1008, 4)
    k_conv_gemm<<<g1, 256>>>(noise);

    k_combine<<<dim3(T_OUT / 256, NROWS), 256>>>();

    k_out_gemm<<<dim3(CCH / 128, T_OUT / 128, 2), 256>>>(vt, sstd, out);
}

// round 3
// speedup vs baseline: 1.8581x; 1.8581x over previous
#include <cuda_runtime.h>
#include <cuda_bf16.h>
#include <cstdint>
#include <cstring>

// Problem constants
#define T_PADDED 65656
#define T_OUT    65536
#define NROWS    768
#define CCH      384
#define NB       168
#define HOP      392
#define OVL      120
#define NCOLS    (NROWS * NB)   // 129024

#define SWZ(x) ((x) ^ (((x) >> 3) & 0x70))

// ---------------- device globals (allocation-free rule) ----------------
__device__ float g_h[512];
__device__ uint4 g_Bc[4 * 7 * 2 * 1024];   // circulant tiles [jt][kc][plane] 16KB planes
__device__ uint4 g_Bw[3 * 6 * 2 * 1024];   // W tiles [dt][kc][plane]
__device__ float g_C[(size_t)NCOLS * 512]; // [col][j]
__device__ float g_y2[(size_t)2 * T_OUT * CCH]; // [n][t][c]

// ---------------- helpers ----------------
__device__ __forceinline__ uint32_t smem_u32(const void* p) {
    uint32_t a;
    asm("{ .reg .u64 t; cvta.to.shared.u64 t, %1; cvt.u32.u64 %0, t; }" : "=r"(a) : "l"(p));
    return a;
}
__device__ __forceinline__ void ldm4(uint32_t addr, uint32_t* r) {
    asm volatile("ldmatrix.sync.aligned.m8n8.x4.shared.b16 {%0,%1,%2,%3}, [%4];"
                 : "=r"(r[0]), "=r"(r[1]), "=r"(r[2]), "=r"(r[3]) : "r"(addr));
}
__device__ __forceinline__ void mma16816(float* c, const uint32_t* a, const uint32_t* b) {
    asm volatile("mma.sync.aligned.m16n8k16.row.col.f32.bf16.bf16.f32 "
                 "{%0,%1,%2,%3},{%4,%5,%6,%7},{%8,%9},{%0,%1,%2,%3};"
                 : "+f"(c[0]), "+f"(c[1]), "+f"(c[2]), "+f"(c[3])
                 : "r"(a[0]), "r"(a[1]), "r"(a[2]), "r"(a[3]), "r"(b[0]), "r"(b[1]));
}
__device__ __forceinline__ unsigned pkb(__nv_bfloat16 a, __nv_bfloat16 b) {
    unsigned short ua, ub;
    memcpy(&ua, &a, 2); memcpy(&ub, &b, 2);
    return ((unsigned)ub << 16) | ua;
}
__device__ __forceinline__ void split4(float4 v, uint2& hi, uint2& lo) {
    __nv_bfloat16 h0 = __float2bfloat16(v.x), h1 = __float2bfloat16(v.y),
                  h2 = __float2bfloat16(v.z), h3 = __float2bfloat16(v.w);
    __nv_bfloat16 l0 = __float2bfloat16(v.x - __bfloat162float(h0));
    __nv_bfloat16 l1 = __float2bfloat16(v.y - __bfloat162float(h1));
    __nv_bfloat16 l2 = __float2bfloat16(v.z - __bfloat162float(h2));
    __nv_bfloat16 l3 = __float2bfloat16(v.w - __bfloat162float(h3));
    hi = make_uint2(pkb(h0, h1), pkb(h2, h3));
    lo = make_uint2(pkb(l0, l1), pkb(l2, l3));
}

// ---------------- kernel 1: h = irfft(H, 512) ----------------
__global__ void k_irfft(const float* __restrict__ H) {
    int j = threadIdx.x;
    float acc = H[0] + ((j & 1) ? -H[256] : H[256]);
    const float w = 6.283185307179586476f / 512.0f;
    for (int m = 1; m < 256; m++) {
        int ph = (m * j) & 511;
        acc += 2.0f * H[m] * cosf(w * (float)ph);
    }
    g_h[j] = acc * (1.0f / 512.0f);
}

// ---------------- kernel 1b: circulant B tiles [j][k] bf16 hi/lo, SW128 ----------------
__global__ void k_build_Bc() {
    __shared__ float sh[512];
    int jt = blockIdx.x, kc = blockIdx.y;
    int tid = threadIdx.x;
    sh[tid] = g_h[tid]; sh[tid + 256] = g_h[tid + 256];
    __syncthreads();
    char* hiB = (char*)g_Bc + (size_t)((jt * 7 + kc) * 2 + 0) * 16384;
    char* loB = (char*)g_Bc + (size_t)((jt * 7 + kc) * 2 + 1) * 16384;
    for (int e = tid; e < 8192; e += 256) {
        int jl = e >> 6, kl = e & 63;
        int k = kc * 64 + kl;
        float v = (k < HOP) ? sh[(jt * 128 + jl - k) & 511] : 0.0f;
        __nv_bfloat16 h = __float2bfloat16(v);
        __nv_bfloat16 l = __float2bfloat16(v - __bfloat162float(h));
        int off = SWZ(jl * 128 + kl * 2);
        *(__nv_bfloat16*)(hiB + off) = h;
        *(__nv_bfloat16*)(loB + off) = l;
    }
}

// ---------------- kernel 1c: W tiles [d][c] = std[c]*vt[c][d], bf16 hi/lo, SW128 ----------------
__global__ void k_build_W(const float* __restrict__ vt, const float* __restrict__ sstd) {
    int dt = blockIdx.x, kc = blockIdx.y;
    int tid = threadIdx.x;
    char* hiB = (char*)g_Bw + (size_t)((dt * 6 + kc) * 2 + 0) * 16384;
    char* loB = (char*)g_Bw + (size_t)((dt * 6 + kc) * 2 + 1) * 16384;
    for (int e = tid; e < 8192; e += 256) {
        int kl = e >> 7, dl = e & 127;
        int c = kc * 64 + kl, d = dt * 128 + dl;
        float v = sstd[c] * vt[c * CCH + d];
        __nv_bfloat16 h = __float2bfloat16(v);
        __nv_bfloat16 l = __float2bfloat16(v - __bfloat162float(h));
        int off = SWZ(dl * 128 + kl * 2);
        *(__nv_bfloat16*)(hiB + off) = h;
        *(__nv_bfloat16*)(loB + off) = l;
    }
}

// ============================================================================
// Warp-MMA GEMM engine: CTA 128(m) x 128(n), K-chunk 64, double-buffered.
// smem buffer s (64KB each): Ahi @s*65536, Alo +16384, Bhi +32768, Blo +49152
// 8 warps: wm = wid>>2 (2), wn = wid&3 (4); warp tile 64m x 32n.
// ============================================================================

struct Frag { float acc[4][4][4]; };

__device__ __forceinline__ void gemm_compute(uint32_t sb, int s, int wm, int wn,
                                             int lane, float acc[4][4][4]) {
    const uint32_t sx = (lane & 7) << 4;
    const int kA_l = (lane & 16) >> 1;                 // 0 or 8
    const int kB_l = lane & 8;                         // 0 or 8
    const int mrow = lane & 15;
    const int nrow = (lane & 7) + ((lane & 16) >> 1);
    const uint32_t aBase = sb + s * 65536 + (wm * 64 + mrow) * 128;
    const uint32_t bBase = sb + s * 65536 + 32768 + (wn * 32 + nrow) * 128;

#pragma unroll
    for (int ks = 0; ks < 4; ks++) {
        const uint32_t ka = ((uint32_t)(ks * 16 + kA_l) * 2) ^ sx;
        const uint32_t kb = ((uint32_t)(ks * 16 + kB_l) * 2) ^ sx;
        uint32_t bh[4][2], bl[4][2];
#pragma unroll
        for (int p = 0; p < 2; p++) {
            uint32_t r[4];
            ldm4(bBase + p * 2048 + kb, r);
            bh[2 * p][0] = r[0]; bh[2 * p][1] = r[1];
            bh[2 * p + 1][0] = r[2]; bh[2 * p + 1][1] = r[3];
            ldm4(bBase + 16384 + p * 2048 + kb, r);
            bl[2 * p][0] = r[0]; bl[2 * p][1] = r[1];
            bl[2 * p + 1][0] = r[2]; bl[2 * p + 1][1] = r[3];
        }
#pragma unroll
        for (int mf = 0; mf < 4; mf++) {
            uint32_t ah[4], al[4];
            ldm4(aBase + mf * 2048 + ka, ah);
            ldm4(aBase + 16384 + mf * 2048 + ka, al);
#pragma unroll
            for (int nf = 0; nf < 4; nf++) {
                mma16816(acc[mf][nf], ah, bh[nf]);
                mma16816(acc[mf][nf], ah, bl[nf]);
                mma16816(acc[mf][nf], al, bh[nf]);
            }
        }
    }
}

// ---------------- kernel 2: conv GEMM: D[col][j] = sum_k noise[col,k] h[(j-k)&511] ----------------
__global__ __launch_bounds__(256) void k_conv_mma(const float* __restrict__ noise) {
    extern __shared__ char smem[];
    const uint32_t sb = smem_u32(smem);
    const int tid = threadIdx.x, lane = tid & 31, wid = tid >> 5;
    const int m0 = blockIdx.x * 128;      // col base
    const int jt = blockIdx.y;            // j tile
    const int wm = wid >> 2, wn = wid & 3;

    // A (noise) load mapping: 8 passes, row = (tid>>4)+p*16, quad = tid&15
    const int arow = tid >> 4;
    const int aq = tid & 15;
    const int arx = ((arow & 7) << 4);    // swizzle xor (row&7 invariant across passes)
    const float* abase[8];
    int atmax[8];
#pragma unroll
    for (int p = 0; p < 8; p++) {
        int col = m0 + arow + p * 16;
        int r = col / NB, b = col - r * NB;
        abase[p] = noise + (size_t)r * T_PADDED + b * HOP;
        atmax[p] = T_PADDED - b * HOP;
    }

    float acc[4][4][4];
#pragma unroll
    for (int i = 0; i < 4; i++)
#pragma unroll
        for (int j = 0; j < 4; j++)
#pragma unroll
            for (int q = 0; q < 4; q++) acc[i][j][q] = 0.0f;

    float4 pf[8];
    // prefetch + store chunk 0
    {
        int kk0 = aq * 4;
#pragma unroll
        for (int p = 0; p < 8; p++)
            pf[p] = (kk0 < atmax[p]) ? *(const float4*)(abase[p] + kk0)
                                     : make_float4(0.f, 0.f, 0.f, 0.f);
        char* ahi = smem;
        char* alo = smem + 16384;
#pragma unroll
        for (int p = 0; p < 8; p++) {
            uint2 hi, lo; split4(pf[p], hi, lo);
            int off = (arow + p * 16) * 128 + ((aq * 8) ^ arx);
            *(uint2*)(ahi + off) = hi;
            *(uint2*)(alo + off) = lo;
        }
        const uint4* srcB = g_Bc + (size_t)(jt * 7) * 2048;
        uint4* dstB = (uint4*)(smem + 32768);
#pragma unroll
        for (int i = 0; i < 8; i++) dstB[tid + i * 256] = srcB[tid + i * 256];
    }
    __syncthreads();

    for (int c = 0; c < 7; c++) {
        const int s = c & 1;
        if (c < 6) {    // issue next chunk's global loads (overlap with MMA)
            int kk0 = (c + 1) * 64 + aq * 4;
            bool kin = kk0 < HOP;
#pragma unroll
            for (int p = 0; p < 8; p++)
                pf[p] = (kin && kk0 < atmax[p]) ? *(const float4*)(abase[p] + kk0)
                                                : make_float4(0.f, 0.f, 0.f, 0.f);
        }
        gemm_compute(sb, s, wm, wn, lane, acc);
        if (c < 6) {
            char* ahi = smem + (s ^ 1) * 65536;
            char* alo = ahi + 16384;
#pragma unroll
            for (int p = 0; p < 8; p++) {
                uint2 hi, lo; split4(pf[p], hi, lo);
                int off = (arow + p * 16) * 128 + ((aq * 8) ^ arx);
                *(uint2*)(ahi + off) = hi;
                *(uint2*)(alo + off) = lo;
            }
            const uint4* srcB = g_Bc + (size_t)((jt * 7 + c + 1)) * 2048;
            uint4* dstB = (uint4*)(smem + (s ^ 1) * 65536 + 32768);
#pragma unroll
            for (int i = 0; i < 8; i++) dstB[tid + i * 256] = srcB[tid + i * 256];
        }
        __syncthreads();
    }

    // epilogue: g_C[col][j]
    const int colb = m0 + wm * 64;
    const int jb = jt * 128 + wn * 32;
#pragma unroll
    for (int mf = 0; mf < 4; mf++) {
        int col0 = colb + mf * 16 + (lane >> 2);
#pragma unroll
        for (int nf = 0; nf < 4; nf++) {
            int j = jb + nf * 8 + (lane & 3) * 2;
            *(float2*)(g_C + (size_t)col0 * 512 + j) = make_float2(acc[mf][nf][0], acc[mf][nf][1]);
            *(float2*)(g_C + (size_t)(col0 + 8) * 512 + j) = make_float2(acc[mf][nf][2], acc[mf][nf][3]);
        }
    }
}

// ---------------- kernel 3: overlap-add combine + transpose -> y2[n][t][c] ----------------
__global__ __launch_bounds__(256) void k_combineT() {
    __shared__ float stage[64][65];
    const int tid = threadIdx.x;
    const int t0 = blockIdx.x * 64;
    const int c0 = blockIdx.y * 64;
    const int nz = blockIdx.z;
    {
        int t_l = tid & 63;
        int t = t0 + t_l;
        int p = t + OVL;
        int b2 = p / HOP;
        int j2 = p - b2 * HOP;
        for (int cc = tid >> 6; cc < 64; cc += 4) {
            int r = nz * CCH + c0 + cc;
            size_t col = (size_t)r * NB + b2;
            float v = g_C[col * 512 + j2];
            if (j2 < OVL) v += g_C[(col - 1) * 512 + j2 + HOP];
            stage[cc][t_l] = v;
        }
    }
    __syncthreads();
    {
        int c_l = tid & 63;
        for (int tt = tid >> 6; tt < 64; tt += 4)
            g_y2[((size_t)nz * T_OUT + t0 + tt) * CCH + c0 + c_l] = stage[c_l][tt];
    }
}

// ---------------- kernel 4: out GEMM: D[t][d] = sum_c y2[t][c] W[d][c] ----------------
__global__ __launch_bounds__(256) void k_out_mma(float* __restrict__ out) {
    extern __shared__ char smem[];
    const uint32_t sb = smem_u32(smem);
    const int tid = threadIdx.x, lane = tid & 31, wid = tid >> 5;
    const int dt = blockIdx.x;
    const int t0 = blockIdx.y * 128;
    const int nz = blockIdx.z;
    const int wm = wid >> 2, wn = wid & 3;

    const int arow = tid >> 4;
    const int aq = tid & 15;
    const int arx = ((arow & 7) << 4);
    const float* abase[8];
#pragma unroll
    for (int p = 0; p < 8; p++)
        abase[p] = g_y2 + ((size_t)nz * T_OUT + t0 + arow + p * 16) * CCH;

    float acc[4][4][4];
#pragma unroll
    for (int i = 0; i < 4; i++)
#pragma unroll
        for (int j = 0; j < 4; j++)
#pragma unroll
            for (int q = 0; q < 4; q++) acc[i][j][q] = 0.0f;

    float4 pf[8];
    {
#pragma unroll
        for (int p = 0; p < 8; p++) pf[p] = *(const float4*)(abase[p] + aq * 4);
        char* ahi = smem;
        char* alo = smem + 16384;
#pragma unroll
        for (int p = 0; p < 8; p++) {
            uint2 hi, lo; split4(pf[p], hi, lo);
            int off = (arow + p * 16) * 128 + ((aq * 8) ^ arx);
            *(uint2*)(ahi + off) = hi;
            *(uint2*)(alo + off) = lo;
        }
        const uint4* srcB = g_Bw + (size_t)(dt * 6) * 2048;
        uint4* dstB = (uint4*)(smem + 32768);
#pragma unroll
        for (int i = 0; i < 8; i++) dstB[tid + i * 256] = srcB[tid + i * 256];
    }
    __syncthreads();

    for (int c = 0; c < 6; c++) {
        const int s = c & 1;
        if (c < 5) {
            int kk0 = (c + 1) * 64 + aq * 4;
#pragma unroll
            for (int p = 0; p < 8; p++) pf[p] = *(const float4*)(abase[p] + kk0);
        }
        gemm_compute(sb, s, wm, wn, lane, acc);
        if (c < 5) {
            char* ahi = smem + (s ^ 1) * 65536;
            char* alo = ahi + 16384;
#pragma unroll
            for (int p = 0; p < 8; p++) {
                uint2 hi, lo; split4(pf[p], hi, lo);
                int off = (arow + p * 16) * 128 + ((aq * 8) ^ arx);
                *(uint2*)(ahi + off) = hi;
                *(uint2*)(alo + off) = lo;
            }
            const uint4* srcB = g_Bw + (size_t)(dt * 6 + c + 1) * 2048;
            uint4* dstB = (uint4*)(smem + (s ^ 1) * 65536 + 32768);
#pragma unroll
            for (int i = 0; i < 8; i++) dstB[tid + i * 256] = srcB[tid + i * 256];
        }
        __syncthreads();
    }

    // epilogue: out[(nz*T + t)*384 + d]
    const int tb = t0 + wm * 64;
    const int db = dt * 128 + wn * 32;
#pragma unroll
    for (int mf = 0; mf < 4; mf++) {
        int t = tb + mf * 16 + (lane >> 2);
        float* ob0 = out + ((size_t)nz * T_OUT + t) * CCH;
        float* ob1 = out + ((size_t)nz * T_OUT + t + 8) * CCH;
#pragma unroll
        for (int nf = 0; nf < 4; nf++) {
            int d = db + nf * 8 + (lane & 3) * 2;
            *(float2*)(ob0 + d) = make_float2(acc[mf][nf][0], acc[mf][nf][1]);
            *(float2*)(ob1 + d) = make_float2(acc[mf][nf][2], acc[mf][nf][3]);
        }
    }
}

// ---------------------------------------------------------------------------
extern "C" void kernel_launch(void* const* d_in, const int* in_sizes, int n_in,
                              void* d_out, int out_size) {
    const float* noise = (const float*)d_in[0];   // [768, 65656]
    const float* sstd  = (const float*)d_in[1];   // [384]
    const float* vt    = (const float*)d_in[2];   // [384, 384]
    const float* H     = (const float*)d_in[3];   // [257]
    float* out = (float*)d_out;                   // [2, 65536, 384]

    cudaFuncSetAttribute(k_conv_mma, cudaFuncAttributeMaxDynamicSharedMemorySize, 131072);
    cudaFuncSetAttribute(k_out_mma,  cudaFuncAttributeMaxDynamicSharedMemorySize, 131072);

    k_irfft<<<1, 512>>>(H);
    k_build_Bc<<<dim3(4, 7), 256>>>();
    k_build_W<<<dim3(3, 6), 256>>>(vt, sstd);
    k_conv_mma<<<dim3(NCOLS / 128, 4), 256, 131072>>>(noise);
    k_combineT<<<dim3(T_OUT / 64, CCH / 64, 2), 256>>>();
    k_out_mma<<<dim3(CCH / 128, T_OUT / 128, 2), 256, 131072>>>(out);
}